// round 6
// baseline (speedup 1.0000x reference)
#include <cuda_runtime.h>
#include <math.h>

// RNNDecoder: per-batch-row independent recurrence -> single persistent launch.
// Each CTA owns MT=32 batch rows; h-state lives in SMEM (k-major) across all
// timesteps. f32x2 packed FMA (PTX-only FFMA2) over m-pairs for 2x fp32 rate.

#define LAT 128
#define HID 1024
#define OBS 64
#define MT  32          // batch rows per CTA
#define NTHREADS 256
#define MS  36          // m-stride (floats) for k-major smem tiles (16B-aligned rows)

typedef unsigned long long u64;

__device__ __forceinline__ u64 dup2(float w) {
    u64 r; unsigned u = __float_as_uint(w);
    asm("mov.b64 %0, {%1, %1};" : "=l"(r) : "r"(u));
    return r;
}
__device__ __forceinline__ void fma2(u64 &acc, u64 a, u64 b) {
    // acc = a * b + acc   (packed 2x f32)
    asm("fma.rn.f32x2 %0, %1, %2, %0;" : "+l"(acc) : "l"(a), "l"(b));
}
__device__ __forceinline__ float2 unpk(u64 v) {
    unsigned lo, hi;
    asm("mov.b64 {%0, %1}, %2;" : "=r"(lo), "=r"(hi) : "l"(v));
    return make_float2(__uint_as_float(lo), __uint_as_float(hi));
}

// Accumulate two output columns (weight rows w0r, w1r) over K against the
// k-major smem tile ks[K][MS]. acc0/acc1: 16 f32x2 m-pair accumulators each.
template<int K>
__device__ __forceinline__ void dot_cols(const float* __restrict__ w0r,
                                         const float* __restrict__ w1r,
                                         const float* __restrict__ ks,
                                         u64* acc0, u64* acc1)
{
    float4 w0 = *(const float4*)w0r;
    float4 w1 = *(const float4*)w1r;
    #pragma unroll 1
    for (int k = 0; k < K; k += 4) {
        int kn = (k + 4 < K) ? (k + 4) : 0;           // prefetch (clamped, uniform)
        float4 nw0 = *(const float4*)(w0r + kn);
        float4 nw1 = *(const float4*)(w1r + kn);
        #pragma unroll
        for (int kk = 0; kk < 4; ++kk) {
            float s0 = (kk==0)?w0.x:(kk==1)?w0.y:(kk==2)?w0.z:w0.w;
            float s1 = (kk==0)?w1.x:(kk==1)?w1.y:(kk==2)?w1.z:w1.w;
            u64 d0 = dup2(s0), d1 = dup2(s1);
            const ulonglong2* hp = (const ulonglong2*)(ks + (k + kk) * MS);
            #pragma unroll
            for (int q = 0; q < 8; ++q) {             // 32 m values = 16 pairs
                ulonglong2 hv = hp[q];                // broadcast LDS.128
                fma2(acc0[2*q    ], hv.x, d0);
                fma2(acc0[2*q + 1], hv.y, d0);
                fma2(acc1[2*q    ], hv.x, d1);
                fma2(acc1[2*q + 1], hv.y, d1);
            }
        }
        w0 = nw0; w1 = nw1;
    }
}

// Output projection: one W_ho row (column o), 8 m rows (4 pairs) at offset moff.
__device__ __forceinline__ void dot_out(const float* __restrict__ wr,
                                        const float* __restrict__ hs,
                                        int moff, u64* yacc)
{
    float4 w = *(const float4*)wr;
    #pragma unroll 1
    for (int j = 0; j < HID; j += 4) {
        int jn = (j + 4 < HID) ? (j + 4) : 0;
        float4 nw = *(const float4*)(wr + jn);
        #pragma unroll
        for (int kk = 0; kk < 4; ++kk) {
            float s = (kk==0)?w.x:(kk==1)?w.y:(kk==2)?w.z:w.w;
            u64 d = dup2(s);
            const ulonglong2* hp = (const ulonglong2*)(hs + (j + kk) * MS + moff);
            ulonglong2 a = hp[0];
            ulonglong2 b = hp[1];
            fma2(yacc[0], a.x, d); fma2(yacc[1], a.y, d);
            fma2(yacc[2], b.x, d); fma2(yacc[3], b.y, d);
        }
        w = nw;
    }
}

__global__ void __launch_bounds__(NTHREADS, 1)
rnn_decoder_kernel(const float* __restrict__ z,
                   const float* __restrict__ W_l2h, const float* __restrict__ b_l2h,
                   const float* __restrict__ W_ih,  const float* __restrict__ b_ih,
                   const float* __restrict__ W_hh,  const float* __restrict__ b_hh,
                   const float* __restrict__ W_ho,  const float* __restrict__ b_ho,
                   float* __restrict__ out, int T)
{
    extern __shared__ float smem[];
    float* h_s  = smem;                   // [HID][MS]  hidden state, k-major
    float* zx_s = h_s + HID * MS;         // [LAT][MS]  (z initially, then x[OBS][MS])
    float* bs_s = zx_s + LAT * MS;        // [HID]      b_ih + b_hh
    float* bo_s = bs_s + HID;             // [OBS]      b_ho

    const int tid = threadIdx.x;
    const int b0  = blockIdx.x * MT;

    // Stage biases and z (k-major transpose) into smem.
    for (int n = tid; n < HID; n += NTHREADS) bs_s[n] = b_ih[n] + b_hh[n];
    if (tid < OBS) bo_s[tid] = b_ho[tid];
    for (int idx = tid; idx < MT * LAT; idx += NTHREADS) {
        int m = idx >> 7;            // / LAT
        int k = idx & (LAT - 1);
        zx_s[k * MS + m] = z[(b0 + m) * LAT + k];   // coalesced LDG
    }
    __syncthreads();

    // ---- h0 = z @ W_l2h^T + b_l2h (no tanh) ----
    {
        u64 acc[2][2][16];
        #pragma unroll
        for (int c = 0; c < 2; ++c) {
            int n0 = c * 512 + tid;
            u64 bv0 = dup2(b_l2h[n0]);
            u64 bv1 = dup2(b_l2h[n0 + 256]);
            #pragma unroll
            for (int p = 0; p < 16; ++p) { acc[c][0][p] = bv0; acc[c][1][p] = bv1; }
            dot_cols<LAT>(W_l2h + n0 * LAT, W_l2h + (n0 + 256) * LAT,
                          zx_s, acc[c][0], acc[c][1]);
        }
        __syncthreads();   // all reads of z done before zx_s is reused for x
        #pragma unroll
        for (int c = 0; c < 2; ++c)
        #pragma unroll
        for (int i = 0; i < 2; ++i) {
            int n = c * 512 + i * 256 + tid;
            float* hrow = h_s + n * MS;
            #pragma unroll
            for (int p = 0; p < 16; ++p) {
                float2 v = unpk(acc[c][i][p]);
                hrow[2*p]     = v.x;
                hrow[2*p + 1] = v.y;
            }
        }
        for (int idx = tid; idx < OBS * MT; idx += NTHREADS) {   // x0 = 0
            int o = idx >> 5, m = idx & (MT - 1);
            zx_s[o * MS + m] = 0.0f;
        }
        __syncthreads();
    }

    const int o  = tid & (OBS - 1);      // output column for phase 2
    const int mg = tid >> 6;             // m-group (4 groups x 8 rows)

    for (int t = 0; t < T; ++t) {
        // ---- phase 1: a = x @ W_ih^T + h @ W_hh^T + (b_ih + b_hh); h = tanh(a) ----
        u64 acc[2][2][16];
        #pragma unroll
        for (int c = 0; c < 2; ++c) {
            int n0 = c * 512 + tid;
            u64 bv0 = dup2(bs_s[n0]);
            u64 bv1 = dup2(bs_s[n0 + 256]);
            #pragma unroll
            for (int p = 0; p < 16; ++p) { acc[c][0][p] = bv0; acc[c][1][p] = bv1; }
            dot_cols<HID>(W_hh + n0 * HID, W_hh + (n0 + 256) * HID,
                          h_s,  acc[c][0], acc[c][1]);
            dot_cols<OBS>(W_ih + n0 * OBS, W_ih + (n0 + 256) * OBS,
                          zx_s, acc[c][0], acc[c][1]);
        }
        __syncthreads();   // everyone finished reading old h and old x
        #pragma unroll
        for (int c = 0; c < 2; ++c)
        #pragma unroll
        for (int i = 0; i < 2; ++i) {
            int n = c * 512 + i * 256 + tid;
            float* hrow = h_s + n * MS;
            #pragma unroll
            for (int p = 0; p < 16; ++p) {
                float2 v = unpk(acc[c][i][p]);
                hrow[2*p]     = tanhf(v.x);
                hrow[2*p + 1] = tanhf(v.y);
            }
        }
        __syncthreads();   // new h visible

        // ---- phase 2: y = h @ W_ho^T + b_ho; emit y; x <- y ----
        u64 yacc[4];
        u64 bo = dup2(bo_s[o]);
        #pragma unroll
        for (int p = 0; p < 4; ++p) yacc[p] = bo;
        dot_out(W_ho + o * HID, h_s, mg * 8, yacc);
        #pragma unroll
        for (int p = 0; p < 4; ++p) {
            float2 v = unpk(yacc[p]);
            int m = mg * 8 + 2 * p;
            size_t base = (size_t)(b0 + m) * (size_t)T * OBS + (size_t)t * OBS + o;
            out[base]                     = v.x;
            out[base + (size_t)T * OBS]   = v.y;   // row m+1
            zx_s[o * MS + m]     = v.x;
            zx_s[o * MS + m + 1] = v.y;
        }
        __syncthreads();   // x update visible before next step's phase 1
    }
}

extern "C" void kernel_launch(void* const* d_in, const int* in_sizes, int n_in,
                              void* d_out, int out_size)
{
    const float* z     = (const float*)d_in[0];
    const float* W_l2h = (const float*)d_in[1];
    const float* b_l2h = (const float*)d_in[2];
    const float* W_ih  = (const float*)d_in[3];
    const float* b_ih  = (const float*)d_in[4];
    const float* W_hh  = (const float*)d_in[5];
    const float* b_hh  = (const float*)d_in[6];
    const float* W_ho  = (const float*)d_in[7];
    const float* b_ho  = (const float*)d_in[8];
    float* out = (float*)d_out;

    int B = in_sizes[0] / LAT;              // 4096
    int T = out_size / (B * OBS);           // 70 (derived host-side, no device read)

    int smem_bytes = (HID * MS + LAT * MS + HID + OBS) * (int)sizeof(float); // 170,240 B
    cudaFuncSetAttribute(rnn_decoder_kernel,
                         cudaFuncAttributeMaxDynamicSharedMemorySize, smem_bytes);

    rnn_decoder_kernel<<<B / MT, NTHREADS, smem_bytes>>>(
        z, W_l2h, b_l2h, W_ih, b_ih, W_hh, b_hh, W_ho, b_ho, out, T);
}

// round 9
// speedup vs baseline: 1.3406x; 1.3406x over previous
#include <cuda_runtime.h>
#include <math.h>

// RNNDecoder persistent CTA kernel, v2.
// Round-6 evidence: L1tex 82% busy (uncoalesced per-thread weight LDG = 32
// wavefronts/instr), fma only 37.7%, regs 253. Fix: pre-transpose weights so
// warps read them coalesced (2 wf/instr), fuse the two column passes into one
// (512 threads, 2 cols/thread -> 64-reg accumulators, no spills).

#define LAT 128
#define HID 1024
#define OBS 64
#define MT  32          // batch rows per CTA
#define NT  512
#define MS  36          // m-stride (floats) for k-major smem tiles (16B aligned)

typedef unsigned long long u64;

// Transposed weights (filled by transpose kernels each launch; __device__
// globals are the allowed scratch mechanism).
__device__ float g_WhhT [HID * HID];   // [k][n]
__device__ float g_WihT [OBS * HID];   // [k][n]
__device__ float g_Wl2hT[LAT * HID];   // [k][n]
__device__ float g_WhoT [HID * OBS];   // [j][o]

__device__ __forceinline__ u64 dup2(float w) {
    u64 r; unsigned u = __float_as_uint(w);
    asm("mov.b64 %0, {%1, %1};" : "=l"(r) : "r"(u));
    return r;
}
__device__ __forceinline__ void fma2(u64 &acc, u64 a, u64 b) {
    asm("fma.rn.f32x2 %0, %1, %2, %0;" : "+l"(acc) : "l"(a), "l"(b));
}
__device__ __forceinline__ float2 unpk(u64 v) {
    unsigned lo, hi;
    asm("mov.b64 {%0, %1}, %2;" : "=r"(lo), "=r"(hi) : "l"(v));
    return make_float2(__uint_as_float(lo), __uint_as_float(hi));
}

// ---- generic 32x32-tiled transpose: dst[C][R] = src[R][C]^T (dims % 32 == 0)
__global__ void transpose_kernel(const float* __restrict__ src,
                                 float* __restrict__ dst, int R, int C)
{
    __shared__ float t[32][33];
    int c0 = blockIdx.x * 32, r0 = blockIdx.y * 32;
    int x = threadIdx.x, y = threadIdx.y;
    #pragma unroll
    for (int i = y; i < 32; i += 8)
        t[i][x] = src[(size_t)(r0 + i) * C + c0 + x];
    __syncthreads();
    #pragma unroll
    for (int i = y; i < 32; i += 8)
        dst[(size_t)(c0 + i) * R + r0 + x] = t[x][i];
}

// Accumulate 2 consecutive columns (n0, n0+1) over K k-values against the
// k-major activation tile ks[K][MS]. wt = transposed weights + n0, row stride
// HID (i.e. element (k, n0) at wt[k*HID]). Coalesced: warp lanes -> 256B.
template<int K>
__device__ __forceinline__ void dotT(const float* __restrict__ wt,
                                     const float* __restrict__ ks,
                                     u64* __restrict__ a0, u64* __restrict__ a1)
{
    float2 cur0 = *(const float2*)(wt + 0 * HID);
    float2 cur1 = *(const float2*)(wt + 1 * HID);
    float2 cur2 = *(const float2*)(wt + 2 * HID);
    float2 cur3 = *(const float2*)(wt + 3 * HID);
    #pragma unroll 1
    for (int k = 0; k < K; k += 4) {
        int kn = (k + 4 < K) ? (k + 4) : 0;            // wrap-clamped prefetch
        float2 nx0 = *(const float2*)(wt + (kn + 0) * HID);
        float2 nx1 = *(const float2*)(wt + (kn + 1) * HID);
        float2 nx2 = *(const float2*)(wt + (kn + 2) * HID);
        float2 nx3 = *(const float2*)(wt + (kn + 3) * HID);
        #pragma unroll
        for (int kk = 0; kk < 4; ++kk) {
            float2 w = (kk == 0) ? cur0 : (kk == 1) ? cur1 : (kk == 2) ? cur2 : cur3;
            u64 d0 = dup2(w.x), d1 = dup2(w.y);
            const ulonglong2* hp = (const ulonglong2*)(ks + (k + kk) * MS);
            #pragma unroll
            for (int q = 0; q < 8; ++q) {              // 32 m = 16 pairs, broadcast LDS.128
                ulonglong2 hv = hp[q];
                fma2(a0[2*q    ], hv.x, d0);
                fma2(a0[2*q + 1], hv.y, d0);
                fma2(a1[2*q    ], hv.x, d1);
                fma2(a1[2*q + 1], hv.y, d1);
            }
        }
        cur0 = nx0; cur1 = nx1; cur2 = nx2; cur3 = nx3;
    }
}

__global__ void __launch_bounds__(NT, 1)
rnn_decoder_kernel(const float* __restrict__ z,
                   const float* __restrict__ b_l2h,
                   const float* __restrict__ b_ih,
                   const float* __restrict__ b_hh,
                   const float* __restrict__ b_ho,
                   float* __restrict__ out, int T)
{
    extern __shared__ float smem[];
    float* h_s  = smem;                   // [HID][MS]  hidden state, k-major
    float* zx_s = h_s + HID * MS;         // [LAT][MS]  z, then x[OBS][MS]
    float* bs_s = zx_s + LAT * MS;        // [HID]      b_ih + b_hh
    float* bo_s = bs_s + HID;             // [OBS]      b_ho

    const int tid = threadIdx.x;
    const int b0  = blockIdx.x * MT;
    const int n0  = 2 * tid;              // this thread's 2 hidden columns

    for (int n = tid; n < HID; n += NT) bs_s[n] = b_ih[n] + b_hh[n];
    if (tid < OBS) bo_s[tid] = b_ho[tid];
    for (int idx = tid; idx < MT * LAT; idx += NT) {
        int m = idx >> 7;                 // / LAT
        int k = idx & (LAT - 1);
        zx_s[k * MS + m] = z[(b0 + m) * LAT + k];
    }
    __syncthreads();

    // ---- h0 = z @ W_l2h^T + b_l2h (no tanh) ----
    {
        u64 a0[16], a1[16];
        u64 bv0 = dup2(b_l2h[n0]), bv1 = dup2(b_l2h[n0 + 1]);
        #pragma unroll
        for (int p = 0; p < 16; ++p) { a0[p] = bv0; a1[p] = bv1; }
        dotT<LAT>(g_Wl2hT + n0, zx_s, a0, a1);
        __syncthreads();                  // reads of z done before zx_s reuse
        float* r0 = h_s + n0 * MS;
        float* r1 = r0 + MS;
        #pragma unroll
        for (int p = 0; p < 16; ++p) {
            float2 v0 = unpk(a0[p]); float2 v1 = unpk(a1[p]);
            r0[2*p] = v0.x; r0[2*p + 1] = v0.y;
            r1[2*p] = v1.x; r1[2*p + 1] = v1.y;
        }
        for (int idx = tid; idx < OBS * MT; idx += NT) {   // x0 = 0
            int o = idx >> 5, m = idx & (MT - 1);
            zx_s[o * MS + m] = 0.0f;
        }
        __syncthreads();
    }

    const int o  = tid & (OBS - 1);       // phase-2 output column
    const int g  = tid >> 6;              // phase-2 m-group (8 groups x 4 rows)
    const int m0 = g * 4;

    for (int t = 0; t < T; ++t) {
        // ---- phase 1: h = tanh(x W_ih^T + h W_hh^T + bias) ----
        u64 a0[16], a1[16];
        u64 bv0 = dup2(bs_s[n0]), bv1 = dup2(bs_s[n0 + 1]);
        #pragma unroll
        for (int p = 0; p < 16; ++p) { a0[p] = bv0; a1[p] = bv1; }
        dotT<HID>(g_WhhT + n0, h_s,  a0, a1);
        dotT<OBS>(g_WihT + n0, zx_s, a0, a1);
        __syncthreads();                  // all reads of old h / old x done
        {
            float* r0 = h_s + n0 * MS;
            float* r1 = r0 + MS;
            #pragma unroll
            for (int p = 0; p < 16; ++p) {
                float2 v0 = unpk(a0[p]); float2 v1 = unpk(a1[p]);
                r0[2*p] = tanhf(v0.x); r0[2*p + 1] = tanhf(v0.y);
                r1[2*p] = tanhf(v1.x); r1[2*p + 1] = tanhf(v1.y);
            }
        }
        __syncthreads();                  // new h visible

        // ---- phase 2: y = h W_ho^T + b_ho; emit; x <- y ----
        {
            u64 y0 = dup2(bo_s[o]), y1 = y0;
            const float* wp = g_WhoT + o;             // stride OBS per j (coalesced)
            float w0c = wp[0*OBS], w1c = wp[1*OBS], w2c = wp[2*OBS], w3c = wp[3*OBS];
            #pragma unroll 1
            for (int j = 0; j < HID; j += 4) {
                int jn = (j + 4 < HID) ? (j + 4) : 0;
                float nw0 = wp[(jn+0)*OBS], nw1 = wp[(jn+1)*OBS];
                float nw2 = wp[(jn+2)*OBS], nw3 = wp[(jn+3)*OBS];
                #pragma unroll
                for (int kk = 0; kk < 4; ++kk) {
                    float s = (kk==0)?w0c:(kk==1)?w1c:(kk==2)?w2c:w3c;
                    u64 d = dup2(s);
                    const ulonglong2* hp =
                        (const ulonglong2*)(h_s + (j + kk) * MS + m0);
                    ulonglong2 hv = hp[0];
                    fma2(y0, hv.x, d);
                    fma2(y1, hv.y, d);
                }
                w0c = nw0; w1c = nw1; w2c = nw2; w3c = nw3;
            }
            float2 v0 = unpk(y0), v1 = unpk(y1);
            size_t base = (size_t)(b0 + m0) * (size_t)T * OBS + (size_t)t * OBS + o;
            size_t st   = (size_t)T * OBS;
            out[base         ] = v0.x;
            out[base +     st] = v0.y;
            out[base + 2 * st] = v1.x;
            out[base + 3 * st] = v1.y;
            *(float4*)(zx_s + o * MS + m0) = make_float4(v0.x, v0.y, v1.x, v1.y);
        }
        __syncthreads();                  // x visible before next step
    }
}

extern "C" void kernel_launch(void* const* d_in, const int* in_sizes, int n_in,
                              void* d_out, int out_size)
{
    const float* z     = (const float*)d_in[0];
    const float* W_l2h = (const float*)d_in[1];
    const float* b_l2h = (const float*)d_in[2];
    const float* W_ih  = (const float*)d_in[3];
    const float* b_ih  = (const float*)d_in[4];
    const float* W_hh  = (const float*)d_in[5];
    const float* b_hh  = (const float*)d_in[6];
    const float* W_ho  = (const float*)d_in[7];
    const float* b_ho  = (const float*)d_in[8];
    float* out = (float*)d_out;

    int B = in_sizes[0] / LAT;              // 4096
    int T = out_size / (B * OBS);           // 70

    float *dWhhT, *dWihT, *dWl2hT, *dWhoT;
    cudaGetSymbolAddress((void**)&dWhhT,  g_WhhT);
    cudaGetSymbolAddress((void**)&dWihT,  g_WihT);
    cudaGetSymbolAddress((void**)&dWl2hT, g_Wl2hT);
    cudaGetSymbolAddress((void**)&dWhoT,  g_WhoT);

    dim3 tb(32, 8);
    transpose_kernel<<<dim3(LAT/32, HID/32), tb>>>(W_l2h, dWl2hT, HID, LAT);
    transpose_kernel<<<dim3(OBS/32, HID/32), tb>>>(W_ih,  dWihT,  HID, OBS);
    transpose_kernel<<<dim3(HID/32, HID/32), tb>>>(W_hh,  dWhhT,  HID, HID);
    transpose_kernel<<<dim3(HID/32, OBS/32), tb>>>(W_ho,  dWhoT,  OBS, HID);

    int smem_bytes = (HID * MS + LAT * MS + HID + OBS) * (int)sizeof(float); // 170,240 B
    cudaFuncSetAttribute(rnn_decoder_kernel,
                         cudaFuncAttributeMaxDynamicSharedMemorySize, smem_bytes);

    rnn_decoder_kernel<<<B / MT, NT, smem_bytes>>>(
        z, b_l2h, b_ih, b_hh, b_ho, out, T);
}

// round 15
// speedup vs baseline: 1.4373x; 1.0721x over previous
#include <cuda_runtime.h>
#include <math.h>

// RNNDecoder persistent CTA kernel, v3 (fp32, proven numerics).
// R6 (MT=32) = 17.06 ms used only 128/148 SMs. v3: MT=28 -> 147 CTAs, one
// wave, per-SM work x28/32. Per-element arithmetic is bit-identical to R6
// (same k-order FFMA2 accumulation, same tanhf, same feedback), so rel_err
// is unchanged at 4.6e-4. Last CTA is ragged: z-rows clamped (pads compute a
// duplicate of row B-1; stores guarded).

#define LAT 128
#define HID 1024
#define OBS 64
#define MT  28          // batch rows per CTA
#define NP  14          // m-pairs per CTA (MT/2)
#define NT  512
#define MS  28          // m-stride (floats); 112B rows, 16B aligned

typedef unsigned long long u64;

// Transposed weights (filled once per launch; __device__ globals = scratch).
__device__ float g_WhhT [HID * HID];   // [k][n]
__device__ float g_WihT [OBS * HID];   // [k][n]
__device__ float g_Wl2hT[LAT * HID];   // [k][n]
__device__ float g_WhoT [HID * OBS];   // [j][o]

__device__ __forceinline__ u64 dup2(float w) {
    u64 r; unsigned u = __float_as_uint(w);
    asm("mov.b64 %0, {%1, %1};" : "=l"(r) : "r"(u));
    return r;
}
__device__ __forceinline__ void fma2(u64 &acc, u64 a, u64 b) {
    asm("fma.rn.f32x2 %0, %1, %2, %0;" : "+l"(acc) : "l"(a), "l"(b));
}
__device__ __forceinline__ float2 unpk(u64 v) {
    unsigned lo, hi;
    asm("mov.b64 {%0, %1}, %2;" : "=r"(lo), "=r"(hi) : "l"(v));
    return make_float2(__uint_as_float(lo), __uint_as_float(hi));
}
__device__ __forceinline__ u64 pk2(float x, float y) {
    u64 r;
    asm("mov.b64 %0, {%1, %2};" : "=l"(r) : "r"(__float_as_uint(x)), "r"(__float_as_uint(y)));
    return r;
}

// ---- 32x32-tiled transpose: dst[C][R] = src[R][C]^T (dims % 32 == 0) ----
__global__ void transpose_kernel(const float* __restrict__ src,
                                 float* __restrict__ dst, int R, int C)
{
    __shared__ float t[32][33];
    int c0 = blockIdx.x * 32, r0 = blockIdx.y * 32;
    int x = threadIdx.x, y = threadIdx.y;
    #pragma unroll
    for (int i = y; i < 32; i += 8)
        t[i][x] = src[(size_t)(r0 + i) * C + c0 + x];
    __syncthreads();
    #pragma unroll
    for (int i = y; i < 32; i += 8)
        dst[(size_t)(c0 + i) * R + r0 + x] = t[x][i];
}

// Accumulate 2 consecutive output columns (n0, n0+1) over K against the
// k-major activation tile ks[K][MS]. wt points at transposed weights + n0
// (element (k, n0) at wt[k*HID]). Warp lanes -> 256B coalesced weight reads.
template<int K>
__device__ __forceinline__ void dotT(const float* __restrict__ wt,
                                     const float* __restrict__ ks,
                                     u64* __restrict__ a0, u64* __restrict__ a1)
{
    float2 cur0 = *(const float2*)(wt + 0 * HID);
    float2 cur1 = *(const float2*)(wt + 1 * HID);
    float2 cur2 = *(const float2*)(wt + 2 * HID);
    float2 cur3 = *(const float2*)(wt + 3 * HID);
    #pragma unroll 1
    for (int k = 0; k < K; k += 4) {
        int kn = (k + 4 < K) ? (k + 4) : 0;            // wrap-clamped prefetch
        float2 nx0 = *(const float2*)(wt + (kn + 0) * HID);
        float2 nx1 = *(const float2*)(wt + (kn + 1) * HID);
        float2 nx2 = *(const float2*)(wt + (kn + 2) * HID);
        float2 nx3 = *(const float2*)(wt + (kn + 3) * HID);
        #pragma unroll
        for (int kk = 0; kk < 4; ++kk) {
            float2 w = (kk == 0) ? cur0 : (kk == 1) ? cur1 : (kk == 2) ? cur2 : cur3;
            u64 d0 = dup2(w.x), d1 = dup2(w.y);
            const ulonglong2* hp = (const ulonglong2*)(ks + (k + kk) * MS);
            #pragma unroll
            for (int q = 0; q < 7; ++q) {              // 14 pairs, broadcast LDS.128
                ulonglong2 hv = hp[q];
                fma2(a0[2*q    ], hv.x, d0);
                fma2(a0[2*q + 1], hv.y, d0);
                fma2(a1[2*q    ], hv.x, d1);
                fma2(a1[2*q + 1], hv.y, d1);
            }
        }
        cur0 = nx0; cur1 = nx1; cur2 = nx2; cur3 = nx3;
    }
}

__global__ void __launch_bounds__(NT, 1)
rnn_decoder_kernel(const float* __restrict__ z,
                   const float* __restrict__ b_l2h,
                   const float* __restrict__ b_ih,
                   const float* __restrict__ b_hh,
                   const float* __restrict__ b_ho,
                   float* __restrict__ out, int T, int B)
{
    extern __shared__ float smem[];
    float* h_s  = smem;                   // [HID][MS]  hidden state, k-major
    float* zx_s = h_s + HID * MS;         // [LAT][MS]  z, then x[OBS][MS]
    float* bs_s = zx_s + LAT * MS;        // [HID]      b_ih + b_hh
    float* bo_s = bs_s + HID;             // [OBS]      b_ho

    const int tid = threadIdx.x;
    const int b0  = blockIdx.x * MT;
    const int n0  = 2 * tid;              // this thread's 2 hidden columns

    for (int n = tid; n < HID; n += NT) bs_s[n] = b_ih[n] + b_hh[n];
    if (tid < OBS) bo_s[tid] = b_ho[tid];
    for (int idx = tid; idx < MT * LAT; idx += NT) {
        int m = idx >> 7;                 // / LAT
        int k = idx & (LAT - 1);
        int gr = b0 + m; if (gr >= B) gr = B - 1;     // clamp ragged tail
        zx_s[k * MS + m] = z[(size_t)gr * LAT + k];
    }
    __syncthreads();

    // ---- h0 = z @ W_l2h^T + b_l2h (no tanh) ----
    {
        u64 a0[NP], a1[NP];
        u64 bv0 = dup2(b_l2h[n0]), bv1 = dup2(b_l2h[n0 + 1]);
        #pragma unroll
        for (int p = 0; p < NP; ++p) { a0[p] = bv0; a1[p] = bv1; }
        dotT<LAT>(g_Wl2hT + n0, zx_s, a0, a1);
        __syncthreads();                  // reads of z done before zx_s reuse
        float* r0 = h_s + n0 * MS;
        float* r1 = r0 + MS;
        #pragma unroll
        for (int p = 0; p < NP; ++p) {
            float2 v0 = unpk(a0[p]); float2 v1 = unpk(a1[p]);
            r0[2*p] = v0.x; r0[2*p + 1] = v0.y;
            r1[2*p] = v1.x; r1[2*p + 1] = v1.y;
        }
        for (int idx = tid; idx < OBS * MT; idx += NT) {   // x0 = 0
            int o = idx / MT, m = idx % MT;
            zx_s[o * MS + m] = 0.0f;
        }
        __syncthreads();
    }

    const int o    = tid & (OBS - 1);     // phase-2 output column
    const int g    = tid >> 6;            // pair-group 0..7
    const int p0   = g;
    const bool has2 = (g + 8 < NP);       // g < 6
    const int p1   = has2 ? g + 8 : g;    // valid pair (dup if !has2)

    for (int t = 0; t < T; ++t) {
        // ---- phase 1: h = tanh(x W_ih^T + h W_hh^T + bias) ----
        u64 a0[NP], a1[NP];
        u64 bv0 = dup2(bs_s[n0]), bv1 = dup2(bs_s[n0 + 1]);
        #pragma unroll
        for (int p = 0; p < NP; ++p) { a0[p] = bv0; a1[p] = bv1; }
        dotT<HID>(g_WhhT + n0, h_s,  a0, a1);
        dotT<OBS>(g_WihT + n0, zx_s, a0, a1);
        __syncthreads();                  // all reads of old h / old x done
        {
            float* r0 = h_s + n0 * MS;
            float* r1 = r0 + MS;
            #pragma unroll
            for (int p = 0; p < NP; ++p) {
                float2 v0 = unpk(a0[p]); float2 v1 = unpk(a1[p]);
                r0[2*p] = tanhf(v0.x); r0[2*p + 1] = tanhf(v0.y);
                r1[2*p] = tanhf(v1.x); r1[2*p + 1] = tanhf(v1.y);
            }
        }
        __syncthreads();                  // new h visible

        // ---- phase 2: y = h W_ho^T + b_ho; emit; x <- y ----
        {
            u64 y0 = dup2(bo_s[o]), y1 = y0;
            const float* wp = g_WhoT + o;             // stride OBS per j (coalesced)
            float w0c = wp[0*OBS], w1c = wp[1*OBS], w2c = wp[2*OBS], w3c = wp[3*OBS];
            #pragma unroll 1
            for (int j = 0; j < HID; j += 4) {
                int jn = (j + 4 < HID) ? (j + 4) : 0;
                float nw0 = wp[(jn+0)*OBS], nw1 = wp[(jn+1)*OBS];
                float nw2 = wp[(jn+2)*OBS], nw3 = wp[(jn+3)*OBS];
                #pragma unroll
                for (int kk = 0; kk < 4; ++kk) {
                    float s = (kk==0)?w0c:(kk==1)?w1c:(kk==2)?w2c:w3c;
                    u64 d = dup2(s);
                    const u64* hr = (const u64*)(h_s + (j + kk) * MS);
                    fma2(y0, hr[p0], d);
                    fma2(y1, hr[p1], d);
                }
                w0c = nw0; w1c = nw1; w2c = nw2; w3c = nw3;
            }
            const size_t st = (size_t)T * OBS;
            {   // pair p0
                float2 v = unpk(y0);
                int m = 2 * p0;
                if (b0 + m < B) {
                    size_t base = (size_t)(b0 + m) * st + (size_t)t * OBS + o;
                    out[base] = v.x;
                    if (b0 + m + 1 < B) out[base + st] = v.y;
                }
                *(u64*)(zx_s + o * MS + m) = pk2(v.x, v.y);
            }
            if (has2) {   // pair p1
                float2 v = unpk(y1);
                int m = 2 * p1;
                if (b0 + m < B) {
                    size_t base = (size_t)(b0 + m) * st + (size_t)t * OBS + o;
                    out[base] = v.x;
                    if (b0 + m + 1 < B) out[base + st] = v.y;
                }
                *(u64*)(zx_s + o * MS + m) = pk2(v.x, v.y);
            }
        }
        __syncthreads();                  // x visible before next step
    }
}

extern "C" void kernel_launch(void* const* d_in, const int* in_sizes, int n_in,
                              void* d_out, int out_size)
{
    const float* z     = (const float*)d_in[0];
    const float* W_l2h = (const float*)d_in[1];
    const float* b_l2h = (const float*)d_in[2];
    const float* W_ih  = (const float*)d_in[3];
    const float* b_ih  = (const float*)d_in[4];
    const float* W_hh  = (const float*)d_in[5];
    const float* b_hh  = (const float*)d_in[6];
    const float* W_ho  = (const float*)d_in[7];
    const float* b_ho  = (const float*)d_in[8];
    float* out = (float*)d_out;

    int B = in_sizes[0] / LAT;              // 4096
    int T = out_size / (B * OBS);           // 70

    float *dWhhT, *dWihT, *dWl2hT, *dWhoT;
    cudaGetSymbolAddress((void**)&dWhhT,  g_WhhT);
    cudaGetSymbolAddress((void**)&dWihT,  g_WihT);
    cudaGetSymbolAddress((void**)&dWl2hT, g_Wl2hT);
    cudaGetSymbolAddress((void**)&dWhoT,  g_WhoT);

    dim3 tb(32, 8);
    transpose_kernel<<<dim3(LAT/32, HID/32), tb>>>(W_l2h, dWl2hT, HID, LAT);
    transpose_kernel<<<dim3(OBS/32, HID/32), tb>>>(W_ih,  dWihT,  HID, OBS);
    transpose_kernel<<<dim3(HID/32, HID/32), tb>>>(W_hh,  dWhhT,  HID, HID);
    transpose_kernel<<<dim3(HID/32, OBS/32), tb>>>(W_ho,  dWhoT,  OBS, HID);

    int smem_bytes = (HID * MS + LAT * MS + HID + OBS) * (int)sizeof(float); // 133,376 B
    cudaFuncSetAttribute(rnn_decoder_kernel,
                         cudaFuncAttributeMaxDynamicSharedMemorySize, smem_bytes);

    int grid = (B + MT - 1) / MT;           // 147 CTAs <= 148 SMs, one wave
    rnn_decoder_kernel<<<grid, NT, smem_bytes>>>(
        z, b_l2h, b_ih, b_hh, b_ho, out, T, B);
}